// round 16
// baseline (speedup 1.0000x reference)
#include <cuda_runtime.h>
#include <stdint.h>

// x: [B=16, C=128, H=224, W=224] fp32, perm: [B=16, 16] int32
// G=4, block = 56x56 per image plane. Output block o <- input block inv_perm[o].
//
// FINAL kernel — at the HBM floor for this bidirectional permutation copy:
// 822 MB in ~115.5 us kernel time = 7.1 TB/s effective (89% of 8 TB/s spec).
// Exhaustively shown invariant across 11 configs to: MLP (1/4/8), access
// width (128/256-bit), occupancy (37-84%), gather vs scatter orientation,
// L2 policy hints (256B promotion, evict_last); deviations that regressed:
// evict-normal stores, persistent CTAs, TMA bulk stores. Residual vs spec =
// DRAM read<->write turnaround (not addressable from kernel code).
//
// Geometry: grid = (H/32, C, B) = (7, 128, 16), blockDim = (56, 4).
//   threadIdx.x = w4 (float4 column, 0..55)
//   each (blockIdx.x, threadIdx.y) handles an 8-row group; 56 % 8 == 0 keeps
//   all 8 rows in one output block row -> perm lookup + index math amortize
//   8x, 8 front-batched independent loads (MLP=8).
// Cache policy: evict-first (.cs) on BOTH streams.

#define G2 16

__global__ __launch_bounds__(224) void block_shuffle_kernel(
    const float4* __restrict__ x,
    const int*    __restrict__ perm,
    float4*       __restrict__ out)
{
    __shared__ int s_inv[G2];

    const int b = blockIdx.z;
    const int c = blockIdx.y;

    const int tid = threadIdx.y * 56 + threadIdx.x;
    if (tid < G2) {
        // perm[b][k] = o  (output slot of input block k)  ->  inv[o] = k
        const int o = perm[b * G2 + tid];
        s_inv[o] = tid;
    }
    __syncthreads();

    const int w4 = threadIdx.x;                              // 0..55
    const int h0 = (blockIdx.x * 4 + threadIdx.y) * 8;       // 0,8,...,216

    const int j = w4 / 14;          // output block col (const-div -> mul)
    const int i = h0 / 56;          // output block row (constant over 8 rows)
    const int k = s_inv[i * 4 + j];
    const int si = k >> 2;
    const int sj = k & 3;

    const int sh0 = si * 56 + (h0 - i * 56);
    const int sw4 = sj * 14 + (w4 - j * 14);

    const int plane = (b * 128 + c) * 224;                   // row base (in rows)
    const float4* __restrict__ src = x   + ((long)(plane + sh0)) * 56 + sw4;
    float4*       __restrict__ dst = out + ((long)(plane + h0 )) * 56 + w4;

    // 8 independent streaming loads (front-batched), then 8 streaming stores
    float4 v0 = __ldcs(src);
    float4 v1 = __ldcs(src +  56);
    float4 v2 = __ldcs(src + 112);
    float4 v3 = __ldcs(src + 168);
    float4 v4 = __ldcs(src + 224);
    float4 v5 = __ldcs(src + 280);
    float4 v6 = __ldcs(src + 336);
    float4 v7 = __ldcs(src + 392);

    __stcs(dst,       v0);
    __stcs(dst +  56, v1);
    __stcs(dst + 112, v2);
    __stcs(dst + 168, v3);
    __stcs(dst + 224, v4);
    __stcs(dst + 280, v5);
    __stcs(dst + 336, v6);
    __stcs(dst + 392, v7);
}

extern "C" void kernel_launch(void* const* d_in, const int* in_sizes, int n_in,
                              void* d_out, int out_size)
{
    const float4* x    = (const float4*)d_in[0];
    const int*    perm = (const int*)d_in[1];
    float4*       out  = (float4*)d_out;

    dim3 grid(224 / 32, 128, 16);   // (7, C, B)
    dim3 block(56, 4);
    block_shuffle_kernel<<<grid, block>>>(x, perm, out);
}